// round 11
// baseline (speedup 1.0000x reference)
#include <cuda_runtime.h>
#include <cuda_bf16.h>

// C[i, j] = sum_k |boxes[i,k] - tpts[j,k]|  -  sigmoid(logits[i, labels[j]])
// NR = bs*Q = 8192 rows, NC = bs*T = 4096 cols. Output row-major fp32 (134 MB).
//
// FINAL — floor established by exhaustive falsification (R3-R10):
//   kernel duration invariant at ~23.3-23.9 us and total at ~27.1-27.4 us across:
//   - geometry: 128thr x (1024c,32r) vs 1024thr x (4096c,27r), occ 38% vs 78%
//   - store width: STG.128 vs STG.256 (v8.b32)
//   - store policy: default, __stcs, __stwt, L2::evict_last/evict_first split
//     (evict_last cross-replay residency REGRESSED: dirty-resident lines slow
//      the LTS store path; no steady-state DRAM saving materialized)
//   Binder: mandatory 134 MB fp32 output vs ~4.9-5.6 TB/s HBM write path.
// Best measured configuration (27.14 us): block = 128 threads covering
// 1024 cols x 32 rows; row data (box float4 + negated sigmoid float2) staged
// in 768 B smem, conflict-free broadcast LDS in the hot loop; targets
// register-cached (2 strided float4 groups/thread -> coalesced 512 B warp
// stores); evict-first streaming stores (__stcs).

#define RPB 32          // rows per block
#define TPB 128         // threads per block; block covers 128*8 = 1024 columns

__device__ __forceinline__ float l1_4(float4 p, float4 t) {
    return fabsf(p.x - t.x) + fabsf(p.y - t.y)
         + fabsf(p.z - t.z) + fabsf(p.w - t.w);
}

__global__ __launch_bounds__(TPB) void cost_kernel(
    const float* __restrict__ logits,  // [NR, 2]
    const float* __restrict__ boxes,   // [NR, 4]
    const float* __restrict__ tpts,    // [NC, 4]
    const int*   __restrict__ tlab,    // [NC]
    float*       __restrict__ out,     // [NR, NC]
    int NR, int NC)
{
    __shared__ float4 s_box[RPB];
    __shared__ float2 s_np[RPB];

    const int NC4 = NC >> 2;
    const int gA  = blockIdx.x * (2 * TPB) + threadIdx.x;   // float4 group A
    const int gB  = gA + TPB;                                // float4 group B
    const int i0  = blockIdx.y * RPB;

    // Stage row data: first 32 threads each handle one row.
    if (threadIdx.x < RPB) {
        int i = i0 + threadIdx.x;
        if (i < NR) {
            s_box[threadIdx.x] = reinterpret_cast<const float4*>(boxes)[i];
            float2 lg = reinterpret_cast<const float2*>(logits)[i];
            float2 np;
            np.x = -1.0f / (1.0f + __expf(-lg.x));
            np.y = -1.0f / (1.0f + __expf(-lg.y));
            s_np[threadIdx.x] = np;
        }
    }

    const float4* tpts4 = reinterpret_cast<const float4*>(tpts);

    // Register-cached targets: 8 columns per thread.
    float4 a0, a1, a2, a3, b0, b1, b2, b3;
    bool sa0 = false, sa1 = false, sa2 = false, sa3 = false;
    bool sb0 = false, sb1 = false, sb2 = false, sb3 = false;
    const bool haveA = (4 * gA + 3 < NC);
    const bool haveB = (4 * gB + 3 < NC);
    if (haveA) {
        a0 = tpts4[4 * gA + 0];  a1 = tpts4[4 * gA + 1];
        a2 = tpts4[4 * gA + 2];  a3 = tpts4[4 * gA + 3];
        sa0 = tlab[4 * gA + 0] != 0;  sa1 = tlab[4 * gA + 1] != 0;
        sa2 = tlab[4 * gA + 2] != 0;  sa3 = tlab[4 * gA + 3] != 0;
    }
    if (haveB) {
        b0 = tpts4[4 * gB + 0];  b1 = tpts4[4 * gB + 1];
        b2 = tpts4[4 * gB + 2];  b3 = tpts4[4 * gB + 3];
        sb0 = tlab[4 * gB + 0] != 0;  sb1 = tlab[4 * gB + 1] != 0;
        sb2 = tlab[4 * gB + 2] != 0;  sb3 = tlab[4 * gB + 3] != 0;
    }

    __syncthreads();

    if (!haveA) return;

    const int rmax = min(RPB, NR - i0);

    #pragma unroll 4
    for (int r = 0; r < rmax; ++r) {
        const int i = i0 + r;
        const float4 p  = s_box[r];   // broadcast LDS, conflict-free
        const float2 np = s_np[r];

        float4 oA;
        oA.x = l1_4(p, a0) + (sa0 ? np.y : np.x);
        oA.y = l1_4(p, a1) + (sa1 ? np.y : np.x);
        oA.z = l1_4(p, a2) + (sa2 ? np.y : np.x);
        oA.w = l1_4(p, a3) + (sa3 ? np.y : np.x);

        float4* orow = reinterpret_cast<float4*>(out) + (size_t)i * NC4;
        __stcs(orow + gA, oA);

        if (haveB) {
            float4 oB;
            oB.x = l1_4(p, b0) + (sb0 ? np.y : np.x);
            oB.y = l1_4(p, b1) + (sb1 ? np.y : np.x);
            oB.z = l1_4(p, b2) + (sb2 ? np.y : np.x);
            oB.w = l1_4(p, b3) + (sb3 ? np.y : np.x);
            __stcs(orow + gB, oB);
        }
    }
}

extern "C" void kernel_launch(void* const* d_in, const int* in_sizes, int n_in,
                              void* d_out, int out_size)
{
    // Inputs (metadata order):
    //   0: pred_logits  [bs, Q, 2]      float32
    //   1: pred_boxes   [bs, Q, 4]      float32
    //   2: tgt_pts      [bs, T, 2, 2]   float32
    //   3: tgt_labels   [bs, T]         int32
    const float* logits = (const float*)d_in[0];
    const float* boxes  = (const float*)d_in[1];
    const float* tpts   = (const float*)d_in[2];
    const int*   tlab   = (const int*)d_in[3];
    float* out = (float*)d_out;

    const int NR = in_sizes[1] / 4;   // bs*Q
    const int NC = in_sizes[3];       // bs*T

    const int cols_per_block = 2 * TPB * 4;   // 1024 columns
    dim3 grid((NC + cols_per_block - 1) / cols_per_block,
              (NR + RPB - 1) / RPB);
    cost_kernel<<<grid, TPB>>>(logits, boxes, tpts, tlab, out, NR, NC);
}

// round 12
// speedup vs baseline: 1.0083x; 1.0083x over previous
#include <cuda_runtime.h>
#include <cuda_bf16.h>

// C[i, j] = sum_k |boxes[i,k] - tpts[j,k]|  -  sigmoid(logits[i, labels[j]])
// NR = bs*Q = 8192 rows, NC = bs*T = 4096 cols. Output row-major fp32 (134 MB).
//
// FINAL — floor established by exhaustive falsification (R3-R11):
//   total pinned at 27.1-27.4 us across five reproductions; kernel duration
//   invariant at ~23.3-23.9 us across:
//   - geometry: 128thr x (1024c,32r) vs 1024thr x (4096c,27r), occ 38% vs 78%
//   - store width: STG.128 vs STG.256 (v8.b32)
//   - store policy: default, __stcs, __stwt, L2::evict_last/evict_first split
//     (evict_last cross-replay residency REGRESSED: dirty-resident lines slow
//      the LTS store path; no steady-state DRAM saving materialized)
//   Binder: mandatory 134 MB fp32 output vs ~4.9 TB/s sustained HBM write BW.
// Best measured configuration (27.14 us): block = 128 threads covering
// 1024 cols x 32 rows; row data (box float4 + negated sigmoid float2) staged
// in 768 B smem, conflict-free broadcast LDS in the hot loop; targets
// register-cached (2 strided float4 groups/thread -> coalesced 512 B warp
// stores); evict-first streaming stores (__stcs).

#define RPB 32          // rows per block
#define TPB 128         // threads per block; block covers 128*8 = 1024 columns

__device__ __forceinline__ float l1_4(float4 p, float4 t) {
    return fabsf(p.x - t.x) + fabsf(p.y - t.y)
         + fabsf(p.z - t.z) + fabsf(p.w - t.w);
}

__global__ __launch_bounds__(TPB) void cost_kernel(
    const float* __restrict__ logits,  // [NR, 2]
    const float* __restrict__ boxes,   // [NR, 4]
    const float* __restrict__ tpts,    // [NC, 4]
    const int*   __restrict__ tlab,    // [NC]
    float*       __restrict__ out,     // [NR, NC]
    int NR, int NC)
{
    __shared__ float4 s_box[RPB];
    __shared__ float2 s_np[RPB];

    const int NC4 = NC >> 2;
    const int gA  = blockIdx.x * (2 * TPB) + threadIdx.x;   // float4 group A
    const int gB  = gA + TPB;                                // float4 group B
    const int i0  = blockIdx.y * RPB;

    // Stage row data: first 32 threads each handle one row.
    if (threadIdx.x < RPB) {
        int i = i0 + threadIdx.x;
        if (i < NR) {
            s_box[threadIdx.x] = reinterpret_cast<const float4*>(boxes)[i];
            float2 lg = reinterpret_cast<const float2*>(logits)[i];
            float2 np;
            np.x = -1.0f / (1.0f + __expf(-lg.x));
            np.y = -1.0f / (1.0f + __expf(-lg.y));
            s_np[threadIdx.x] = np;
        }
    }

    const float4* tpts4 = reinterpret_cast<const float4*>(tpts);

    // Register-cached targets: 8 columns per thread.
    float4 a0, a1, a2, a3, b0, b1, b2, b3;
    bool sa0 = false, sa1 = false, sa2 = false, sa3 = false;
    bool sb0 = false, sb1 = false, sb2 = false, sb3 = false;
    const bool haveA = (4 * gA + 3 < NC);
    const bool haveB = (4 * gB + 3 < NC);
    if (haveA) {
        a0 = tpts4[4 * gA + 0];  a1 = tpts4[4 * gA + 1];
        a2 = tpts4[4 * gA + 2];  a3 = tpts4[4 * gA + 3];
        sa0 = tlab[4 * gA + 0] != 0;  sa1 = tlab[4 * gA + 1] != 0;
        sa2 = tlab[4 * gA + 2] != 0;  sa3 = tlab[4 * gA + 3] != 0;
    }
    if (haveB) {
        b0 = tpts4[4 * gB + 0];  b1 = tpts4[4 * gB + 1];
        b2 = tpts4[4 * gB + 2];  b3 = tpts4[4 * gB + 3];
        sb0 = tlab[4 * gB + 0] != 0;  sb1 = tlab[4 * gB + 1] != 0;
        sb2 = tlab[4 * gB + 2] != 0;  sb3 = tlab[4 * gB + 3] != 0;
    }

    __syncthreads();

    if (!haveA) return;

    const int rmax = min(RPB, NR - i0);

    #pragma unroll 4
    for (int r = 0; r < rmax; ++r) {
        const int i = i0 + r;
        const float4 p  = s_box[r];   // broadcast LDS, conflict-free
        const float2 np = s_np[r];

        float4 oA;
        oA.x = l1_4(p, a0) + (sa0 ? np.y : np.x);
        oA.y = l1_4(p, a1) + (sa1 ? np.y : np.x);
        oA.z = l1_4(p, a2) + (sa2 ? np.y : np.x);
        oA.w = l1_4(p, a3) + (sa3 ? np.y : np.x);

        float4* orow = reinterpret_cast<float4*>(out) + (size_t)i * NC4;
        __stcs(orow + gA, oA);

        if (haveB) {
            float4 oB;
            oB.x = l1_4(p, b0) + (sb0 ? np.y : np.x);
            oB.y = l1_4(p, b1) + (sb1 ? np.y : np.x);
            oB.z = l1_4(p, b2) + (sb2 ? np.y : np.x);
            oB.w = l1_4(p, b3) + (sb3 ? np.y : np.x);
            __stcs(orow + gB, oB);
        }
    }
}

extern "C" void kernel_launch(void* const* d_in, const int* in_sizes, int n_in,
                              void* d_out, int out_size)
{
    // Inputs (metadata order):
    //   0: pred_logits  [bs, Q, 2]      float32
    //   1: pred_boxes   [bs, Q, 4]      float32
    //   2: tgt_pts      [bs, T, 2, 2]   float32
    //   3: tgt_labels   [bs, T]         int32
    const float* logits = (const float*)d_in[0];
    const float* boxes  = (const float*)d_in[1];
    const float* tpts   = (const float*)d_in[2];
    const int*   tlab   = (const int*)d_in[3];
    float* out = (float*)d_out;

    const int NR = in_sizes[1] / 4;   // bs*Q
    const int NC = in_sizes[3];       // bs*T

    const int cols_per_block = 2 * TPB * 4;   // 1024 columns
    dim3 grid((NC + cols_per_block - 1) / cols_per_block,
              (NR + RPB - 1) / RPB);
    cost_kernel<<<grid, TPB>>>(logits, boxes, tpts, tlab, out, NR, NC);
}

// round 13
// speedup vs baseline: 1.0094x; 1.0012x over previous
#include <cuda_runtime.h>
#include <cuda_bf16.h>

// C[i, j] = sum_k |boxes[i,k] - tpts[j,k]|  -  sigmoid(logits[i, labels[j]])
// NR = bs*Q = 8192 rows, NC = bs*T = 4096 cols. Output row-major fp32 (134 MB).
//
// FINAL — floor established by exhaustive falsification (R3-R12):
//   total pinned at 27.1-27.4 us across six reproductions; kernel duration
//   invariant at ~23.3-24.0 us across:
//   - geometry: 128thr x (1024c,32r) vs 1024thr x (4096c,27r), occ 38% vs 78%
//   - store width: STG.128 vs STG.256 (v8.b32)
//   - store policy: default, __stcs, __stwt, L2::evict_last/evict_first split
//     (evict_last cross-replay residency REGRESSED: dirty-resident lines slow
//      the LTS store path; no steady-state DRAM saving materialized)
//   Binder: mandatory 134 MB fp32 output vs ~4.9 TB/s sustained HBM write BW.
// Best measured configuration (27.14 us): block = 128 threads covering
// 1024 cols x 32 rows; row data (box float4 + negated sigmoid float2) staged
// in 768 B smem, conflict-free broadcast LDS in the hot loop; targets
// register-cached (2 strided float4 groups/thread -> coalesced 512 B warp
// stores); evict-first streaming stores (__stcs).

#define RPB 32          // rows per block
#define TPB 128         // threads per block; block covers 128*8 = 1024 columns

__device__ __forceinline__ float l1_4(float4 p, float4 t) {
    return fabsf(p.x - t.x) + fabsf(p.y - t.y)
         + fabsf(p.z - t.z) + fabsf(p.w - t.w);
}

__global__ __launch_bounds__(TPB) void cost_kernel(
    const float* __restrict__ logits,  // [NR, 2]
    const float* __restrict__ boxes,   // [NR, 4]
    const float* __restrict__ tpts,    // [NC, 4]
    const int*   __restrict__ tlab,    // [NC]
    float*       __restrict__ out,     // [NR, NC]
    int NR, int NC)
{
    __shared__ float4 s_box[RPB];
    __shared__ float2 s_np[RPB];

    const int NC4 = NC >> 2;
    const int gA  = blockIdx.x * (2 * TPB) + threadIdx.x;   // float4 group A
    const int gB  = gA + TPB;                                // float4 group B
    const int i0  = blockIdx.y * RPB;

    // Stage row data: first 32 threads each handle one row.
    if (threadIdx.x < RPB) {
        int i = i0 + threadIdx.x;
        if (i < NR) {
            s_box[threadIdx.x] = reinterpret_cast<const float4*>(boxes)[i];
            float2 lg = reinterpret_cast<const float2*>(logits)[i];
            float2 np;
            np.x = -1.0f / (1.0f + __expf(-lg.x));
            np.y = -1.0f / (1.0f + __expf(-lg.y));
            s_np[threadIdx.x] = np;
        }
    }

    const float4* tpts4 = reinterpret_cast<const float4*>(tpts);

    // Register-cached targets: 8 columns per thread.
    float4 a0, a1, a2, a3, b0, b1, b2, b3;
    bool sa0 = false, sa1 = false, sa2 = false, sa3 = false;
    bool sb0 = false, sb1 = false, sb2 = false, sb3 = false;
    const bool haveA = (4 * gA + 3 < NC);
    const bool haveB = (4 * gB + 3 < NC);
    if (haveA) {
        a0 = tpts4[4 * gA + 0];  a1 = tpts4[4 * gA + 1];
        a2 = tpts4[4 * gA + 2];  a3 = tpts4[4 * gA + 3];
        sa0 = tlab[4 * gA + 0] != 0;  sa1 = tlab[4 * gA + 1] != 0;
        sa2 = tlab[4 * gA + 2] != 0;  sa3 = tlab[4 * gA + 3] != 0;
    }
    if (haveB) {
        b0 = tpts4[4 * gB + 0];  b1 = tpts4[4 * gB + 1];
        b2 = tpts4[4 * gB + 2];  b3 = tpts4[4 * gB + 3];
        sb0 = tlab[4 * gB + 0] != 0;  sb1 = tlab[4 * gB + 1] != 0;
        sb2 = tlab[4 * gB + 2] != 0;  sb3 = tlab[4 * gB + 3] != 0;
    }

    __syncthreads();

    if (!haveA) return;

    const int rmax = min(RPB, NR - i0);

    #pragma unroll 4
    for (int r = 0; r < rmax; ++r) {
        const int i = i0 + r;
        const float4 p  = s_box[r];   // broadcast LDS, conflict-free
        const float2 np = s_np[r];

        float4 oA;
        oA.x = l1_4(p, a0) + (sa0 ? np.y : np.x);
        oA.y = l1_4(p, a1) + (sa1 ? np.y : np.x);
        oA.z = l1_4(p, a2) + (sa2 ? np.y : np.x);
        oA.w = l1_4(p, a3) + (sa3 ? np.y : np.x);

        float4* orow = reinterpret_cast<float4*>(out) + (size_t)i * NC4;
        __stcs(orow + gA, oA);

        if (haveB) {
            float4 oB;
            oB.x = l1_4(p, b0) + (sb0 ? np.y : np.x);
            oB.y = l1_4(p, b1) + (sb1 ? np.y : np.x);
            oB.z = l1_4(p, b2) + (sb2 ? np.y : np.x);
            oB.w = l1_4(p, b3) + (sb3 ? np.y : np.x);
            __stcs(orow + gB, oB);
        }
    }
}

extern "C" void kernel_launch(void* const* d_in, const int* in_sizes, int n_in,
                              void* d_out, int out_size)
{
    // Inputs (metadata order):
    //   0: pred_logits  [bs, Q, 2]      float32
    //   1: pred_boxes   [bs, Q, 4]      float32
    //   2: tgt_pts      [bs, T, 2, 2]   float32
    //   3: tgt_labels   [bs, T]         int32
    const float* logits = (const float*)d_in[0];
    const float* boxes  = (const float*)d_in[1];
    const float* tpts   = (const float*)d_in[2];
    const int*   tlab   = (const int*)d_in[3];
    float* out = (float*)d_out;

    const int NR = in_sizes[1] / 4;   // bs*Q
    const int NC = in_sizes[3];       // bs*T

    const int cols_per_block = 2 * TPB * 4;   // 1024 columns
    dim3 grid((NC + cols_per_block - 1) / cols_per_block,
              (NR + RPB - 1) / RPB);
    cost_kernel<<<grid, TPB>>>(logits, boxes, tpts, tlab, out, NR, NC);
}